// round 1
// baseline (speedup 1.0000x reference)
#include <cuda_runtime.h>

#define NSAMP 64
#define HID   256
#define PAD1  66      // h1T row stride (floats)
#define PAD2  260     // h2 row stride (floats)
#define KSLAB 32      // W2 k-rows per shared slab
#define STEPZ (5.0f/63.0f)

// shared layout (floats)
#define SM_W2OFF  (HID*PAD1)              // 16896
#define SM_AUXOFF (SM_W2OFF + KSLAB*HID)  // 16896+8192 = 25088
#define SMEM_FLOATS (SM_AUXOFF + 512)     // 25600
#define SMEM_BYTES  (SMEM_FLOATS * 4)     // 102400

__device__ __forceinline__ float2 ffma2(float2 a, float2 b, float2 c) {
    float2 d;
    asm("fma.rn.f32x2 %0, %1, %2, %3;"
        : "=l"(*(unsigned long long*)&d)
        : "l"(*(unsigned long long*)&a),
          "l"(*(unsigned long long*)&b),
          "l"(*(unsigned long long*)&c));
    return d;
}

__global__ __launch_bounds__(256, 2)
void nerf_fused_kernel(const float* __restrict__ x_pix,
                       const float* __restrict__ intr,
                       const float* __restrict__ c2w,
                       const float* __restrict__ W1, const float* __restrict__ b1,
                       const float* __restrict__ W2, const float* __restrict__ b2,
                       const float* __restrict__ W3, const float* __restrict__ b3,
                       float* __restrict__ out, int nrays, int R)
{
    extern __shared__ float sm[];
    float* h1T  = sm;                 // [256][66]  (aliased by h2s later)
    float* w2s  = sm + SM_W2OFF;      // [KSLAB][256]
    float* out4 = sm + SM_AUXOFF;     // [64][4]
    float* alph = out4 + 256;         // [64]
    float* rr_  = alph + 64;          // [64]
    float* rg_  = rr_ + 64;           // [64]
    float* rb_  = rg_ + 64;           // [64]
    float* h2s  = sm;                 // alias of h1T: [64][260] = 66560B <= 67584B

    const int tid = threadIdx.x;
    const int ray = blockIdx.x;
    const int b   = ray / R;

    // ---------------- ray setup (redundant per-thread, cheap) ----------------
    const float* Km = intr + b * 9;
    float a00=Km[0],a01=Km[1],a02=Km[2];
    float a10=Km[3],a11=Km[4],a12=Km[5];
    float a20=Km[6],a21=Km[7],a22=Km[8];
    float i00 = a11*a22 - a12*a21;
    float i01 = a02*a21 - a01*a22;
    float i02 = a01*a12 - a02*a11;
    float i10 = a12*a20 - a10*a22;
    float i11 = a00*a22 - a02*a20;
    float i12 = a02*a10 - a00*a12;
    float i20 = a10*a21 - a11*a20;
    float i21 = a01*a20 - a00*a21;
    float i22 = a00*a11 - a01*a10;
    float det = a00*i00 + a01*i10 + a02*i20;
    float idet = 1.0f / det;

    float px = x_pix[ray*2 + 0];
    float py = x_pix[ray*2 + 1];
    float dcx = (i00*px + i01*py + i02) * idet;
    float dcy = (i10*px + i11*py + i12) * idet;
    float dcz = (i20*px + i21*py + i22) * idet;

    const float* M = c2w + b * 16;  // row-major 4x4
    float rdx = M[0]*dcx + M[1]*dcy + M[2]*dcz;
    float rdy = M[4]*dcx + M[5]*dcy + M[6]*dcz;
    float rdz = M[8]*dcx + M[9]*dcy + M[10]*dcz;
    float rox = M[3], roy = M[7], roz = M[11];

    // ---------------- layer 1: thread tid = hidden unit j ----------------
    {
        int j = tid;
        float w0 = W1[j], w1 = W1[HID + j], w2v = W1[2*HID + j];
        float abase = rox*w0 + roy*w1 + roz*w2v + b1[j];
        float cmul  = rdx*w0 + rdy*w1 + rdz*w2v;
        float* row = &h1T[j * PAD1];
        #pragma unroll
        for (int s = 0; s < NSAMP; s++) {
            float z = fmaf((float)s, STEPZ, 1.0f);
            float h = fmaf(z, cmul, abase);
            row[s] = fmaxf(h, 0.0f);
        }
    }

    // ---------------- layer 2: 64x256x256, register tiled, f32x2 ----------------
    const int tx = tid & 31;      // j-tile
    const int ty = tid >> 5;      // s-tile
    const int j0 = tx * 8;
    const int s0 = ty * 8;

    float2 acc[8][4];
    #pragma unroll
    for (int s = 0; s < 8; s++)
        #pragma unroll
        for (int jp = 0; jp < 4; jp++)
            acc[s][jp] = make_float2(0.f, 0.f);

    for (int kb = 0; kb < HID; kb += KSLAB) {
        __syncthreads();  // iter 0: h1T ready; later: w2s consumers done
        {
            const float4* src = (const float4*)(W2 + kb * HID);
            float4* dst = (float4*)w2s;
            #pragma unroll
            for (int i = 0; i < (KSLAB * HID / 4) / 256; i++)
                dst[tid + i * 256] = src[tid + i * 256];
        }
        __syncthreads();

        #pragma unroll 4
        for (int kk = 0; kk < KSLAB; kk++) {
            const int k = kb + kk;
            const float2* hp = (const float2*)&h1T[k * PAD1 + s0];
            float2 h01 = hp[0], h23 = hp[1], h45 = hp[2], h67 = hp[3];
            const float4* wp = (const float4*)&w2s[kk * HID + j0];
            float4 wA = wp[0], wB = wp[1];
            float2 w01 = make_float2(wA.x, wA.y);
            float2 w23 = make_float2(wA.z, wA.w);
            float2 w45 = make_float2(wB.x, wB.y);
            float2 w67 = make_float2(wB.z, wB.w);
            float hs[8] = {h01.x,h01.y,h23.x,h23.y,h45.x,h45.y,h67.x,h67.y};
            #pragma unroll
            for (int s = 0; s < 8; s++) {
                float2 hd = make_float2(hs[s], hs[s]);
                acc[s][0] = ffma2(hd, w01, acc[s][0]);
                acc[s][1] = ffma2(hd, w23, acc[s][1]);
                acc[s][2] = ffma2(hd, w45, acc[s][2]);
                acc[s][3] = ffma2(hd, w67, acc[s][3]);
            }
        }
    }

    // bias + relu + store h2 (aliases h1T; all reads of h1T finished)
    __syncthreads();
    {
        float bj[8];
        #pragma unroll
        for (int j = 0; j < 8; j++) bj[j] = b2[j0 + j];
        #pragma unroll
        for (int s = 0; s < 8; s++) {
            float* dst = &h2s[(s0 + s) * PAD2 + j0];
            #pragma unroll
            for (int jp = 0; jp < 4; jp++) {
                dst[2*jp+0] = fmaxf(acc[s][jp].x + bj[2*jp+0], 0.0f);
                dst[2*jp+1] = fmaxf(acc[s][jp].y + bj[2*jp+1], 0.0f);
            }
        }
    }
    __syncthreads();

    // ---------------- layer 3: thread = (sample, channel) ----------------
    {
        const int s3 = tid >> 2;
        const int cc = tid & 3;
        const float* hrow = &h2s[s3 * PAD2];
        float acc3 = b3[cc];
        #pragma unroll 8
        for (int k = 0; k < HID; k++)
            acc3 = fmaf(hrow[k], __ldg(&W3[k * 4 + cc]), acc3);
        out4[tid] = acc3;  // out4[s*4 + c]
    }
    __syncthreads();

    // ---------------- epilogue: alpha/sigmoid parallel, scan serial ----------------
    if (tid < NSAMP) {
        const int s = tid;
        float o0 = out4[s*4+0], o1 = out4[s*4+1], o2 = out4[s*4+2], o3 = out4[s*4+3];
        float z  = fmaf((float)s, STEPZ, 1.0f);
        float zn = (s < NSAMP-1) ? fmaf((float)(s+1), STEPZ, 1.0f) : 1000.0f;
        float dist = zn - z;
        float sg = fmaxf(o0, 0.0f);
        alph[s] = 1.0f - __expf(-sg * dist);
        rr_[s] = 1.0f / (1.0f + __expf(-o1));
        rg_[s] = 1.0f / (1.0f + __expf(-o2));
        rb_[s] = 1.0f / (1.0f + __expf(-o3));
    }
    __syncthreads();

    if (tid == 0) {
        float T = 1.0f, Rc = 0.f, Gc = 0.f, Bc = 0.f, D = 0.f, A = 0.f;
        #pragma unroll
        for (int s = 0; s < NSAMP; s++) {
            float al = alph[s];
            T *= (1.0f - al);          // inclusive cumprod (matches reference)
            float w = al * T;
            Rc = fmaf(w, rr_[s], Rc);
            Gc = fmaf(w, rg_[s], Gc);
            Bc = fmaf(w, rb_[s], Bc);
            float z = fmaf((float)s, STEPZ, 1.0f);
            D = fmaf(w, z, D);
            A += w;
        }
        float bg = 1.0f - A;           // white background
        out[ray*3 + 0] = Rc + bg;
        out[ray*3 + 1] = Gc + bg;
        out[ray*3 + 2] = Bc + bg;
        out[nrays*3 + ray] = D;        // depth after all rgb
    }
}

extern "C" void kernel_launch(void* const* d_in, const int* in_sizes, int n_in,
                              void* d_out, int out_size)
{
    const float* x_pix = (const float*)d_in[0];
    const float* intr  = (const float*)d_in[1];
    const float* c2w   = (const float*)d_in[2];
    const float* W1    = (const float*)d_in[3];
    const float* b1    = (const float*)d_in[4];
    const float* W2    = (const float*)d_in[5];
    const float* b2    = (const float*)d_in[6];
    const float* W3    = (const float*)d_in[7];
    const float* b3    = (const float*)d_in[8];
    float* out = (float*)d_out;

    int nrays = in_sizes[0] / 2;      // B*R
    int B     = in_sizes[1] / 9;
    int R     = nrays / B;

    cudaFuncSetAttribute(nerf_fused_kernel,
                         cudaFuncAttributeMaxDynamicSharedMemorySize, SMEM_BYTES);

    nerf_fused_kernel<<<nrays, 256, SMEM_BYTES>>>(
        x_pix, intr, c2w, W1, b1, W2, b2, W3, b3, out, nrays, R);
}

// round 3
// speedup vs baseline: 3.7846x; 3.7846x over previous
#include <cuda_runtime.h>
#include <cstdint>

#define NS     64
#define HID    256
#define STEPZ  (5.0f/63.0f)
#define NSLAB  8
#define KPAD   264                      // floats per k-row (256 + 8 pad)
#define SLAB_FLOATS (32*KPAD)           // 8448
#define SLAB_BYTES  (SLAB_FLOATS*4)     // 33792

// ---- shared memory byte offsets ----
#define OFF_SLAB 0                         // 2 x 33792 = 67584
#define OFF_AC   (2*SLAB_BYTES)            // 67584 : float2 ac[256]   (2048)
#define OFF_W3   (OFF_AC + 2048)           // 69632 : float4 W3[256]   (4096)
#define OFF_B2   (OFF_W3 + 4096)           // 73728 : float b2[256]    (1024)
#define OFF_RED  (OFF_B2 + 1024)           // 74752 : float red[4][64][4] (4096)
#define OFF_AUX  (OFF_RED + 4096)          // 78848 : alpha/r/g/b [64] (1024)
#define OFF_MBAR (OFF_AUX + 1024)          // 79872 : 2 mbarriers
#define SMEM_TOTAL (OFF_MBAR + 32)         // 79904

// W2 pre-arranged: [slab][kk][KPAD] tf32 bits
__device__ __align__(16) uint32_t W2s_g[NSLAB * SLAB_FLOATS];

// =================== PTX helpers (base-target only) ===================
__device__ __forceinline__ uint32_t smem_u32(const void* p) {
    uint32_t a;
    asm("{ .reg .u64 t; cvta.to.shared.u64 t, %1; cvt.u32.u64 %0, t; }" : "=r"(a) : "l"(p));
    return a;
}
#define MBAR_INIT(a, c) \
    asm volatile("mbarrier.init.shared.b64 [%0], %1;" :: "r"(a), "r"((uint32_t)(c)) : "memory")
#define MBAR_EXPECT_TX(a, b) \
    asm volatile("mbarrier.arrive.expect_tx.shared.b64 _, [%0], %1;" :: "r"(a), "r"((uint32_t)(b)) : "memory")
#define MBAR_INVAL(a) \
    asm volatile("mbarrier.inval.shared.b64 [%0];" :: "r"(a) : "memory")
#define MBAR_WAIT(a, ph) do {                                                   \
    uint32_t _m = (a); uint32_t _p = (ph); uint32_t _d;                         \
    asm volatile("{\n\t.reg .pred p;\n\t"                                       \
        "mbarrier.try_wait.parity.acquire.cta.shared::cta.b64 p, [%1], %2;\n\t" \
        "selp.b32 %0, 1, 0, p;\n\t}" : "=r"(_d) : "r"(_m), "r"(_p) : "memory"); \
    if (!_d) {                                                                  \
        asm volatile("{\n\t.reg .pred P1;\n\t"                                  \
        "WL_%=:\n\t"                                                            \
        "mbarrier.try_wait.parity.acquire.cta.shared::cta.b64 P1, [%0], %1, 0x989680;\n\t" \
        "@P1 bra.uni WD_%=;\n\t bra.uni WL_%=;\n\t WD_%=:\n\t}"                 \
        :: "r"(_m), "r"(_p) : "memory");                                        \
    } } while (0)

__device__ __forceinline__ void bulk_g2s(uint32_t dst, const void* src, uint32_t bytes, uint32_t mbar) {
    asm volatile("cp.async.bulk.shared::cta.global.mbarrier::complete_tx::bytes [%0], [%1], %2, [%3];"
                 :: "r"(dst), "l"(src), "r"(bytes), "r"(mbar) : "memory");
}
__device__ __forceinline__ uint32_t f2tf32(float v) {
    uint32_t b; asm("cvt.rna.tf32.f32 %0, %1;" : "=r"(b) : "f"(v)); return b;
}
__device__ __forceinline__ void mma8(float* d, const uint32_t* a, uint32_t b0, uint32_t b1) {
    asm volatile("mma.sync.aligned.m16n8k8.row.col.f32.tf32.tf32.f32 "
        "{%0,%1,%2,%3}, {%4,%5,%6,%7}, {%8,%9}, {%0,%1,%2,%3};"
        : "+f"(d[0]), "+f"(d[1]), "+f"(d[2]), "+f"(d[3])
        : "r"(a[0]), "r"(a[1]), "r"(a[2]), "r"(a[3]), "r"(b0), "r"(b1));
}
__device__ __forceinline__ float2 ffma2(float2 a, float2 b, float2 c) {
    float2 d;
    asm("fma.rn.f32x2 %0, %1, %2, %3;"
        : "=l"(*(unsigned long long*)&d)
        : "l"(*(unsigned long long*)&a), "l"(*(unsigned long long*)&b), "l"(*(unsigned long long*)&c));
    return d;
}

// =================== kernel 1: rearrange W2 (tf32, pad-264) ===================
__global__ void arrange_w2_kernel(const float* __restrict__ W2) {
    int idx = blockIdx.x * 256 + threadIdx.x;       // 0..65535
    int k = idx >> 8, n = idx & 255;
    int slab = k >> 5, kk = k & 31;
    W2s_g[slab * SLAB_FLOATS + kk * KPAD + n] = f2tf32(W2[k * HID + n]);
}

// =================== kernel 2: fused renderer (1 ray / CTA) ===================
__global__ __launch_bounds__(256, 2)
void nerf_mma_kernel(const float* __restrict__ x_pix,
                     const float* __restrict__ intr,
                     const float* __restrict__ c2w,
                     const float* __restrict__ W1, const float* __restrict__ b1,
                     const float* __restrict__ b2,
                     const float* __restrict__ W3, const float* __restrict__ b3,
                     float* __restrict__ out, int nrays, int R)
{
    extern __shared__ char sm[];
    const uint32_t smb = smem_u32(sm);
    float2* ac_s = (float2*)(sm + OFF_AC);
    float4* w3_s = (float4*)(sm + OFF_W3);
    float*  b2_s = (float*)(sm + OFF_B2);
    float*  red  = (float*)(sm + OFF_RED);      // [4 warpN][64 s][4 ch]
    float*  alph = (float*)(sm + OFF_AUX);
    float*  rr_  = alph + 64; float* gg_ = rr_ + 64; float* bb_ = gg_ + 64;

    const uint32_t mb0 = smb + OFF_MBAR;        // full[buf] at +0, +8

    const int tid  = threadIdx.x;
    const int lane = tid & 31, warp = tid >> 5;
    const int warpM = warp >> 2, warpN = warp & 3;   // 2 x 4 warp grid
    const int g = lane >> 2, tig = lane & 3;

    // --- mbarrier init + kick first two slab copies ---
    if (tid == 0) {
        MBAR_INIT(mb0, 1);
        MBAR_INIT(mb0 + 8, 1);
        MBAR_EXPECT_TX(mb0, SLAB_BYTES);
        bulk_g2s(smb + OFF_SLAB, &W2s_g[0], SLAB_BYTES, mb0);
        MBAR_EXPECT_TX(mb0 + 8, SLAB_BYTES);
        bulk_g2s(smb + OFF_SLAB + SLAB_BYTES, &W2s_g[SLAB_FLOATS], SLAB_BYTES, mb0 + 8);
    }

    // --- setup: (a,c) table, stage W3/b2, zero reduction buffer ---
    {
        const int ray = blockIdx.x;
        const int b   = ray / R;
        const float* Km = intr + b * 9;
        float a00=Km[0],a01=Km[1],a02=Km[2],a10=Km[3],a11=Km[4],a12=Km[5],a20=Km[6],a21=Km[7],a22=Km[8];
        float i00=a11*a22-a12*a21, i01=a02*a21-a01*a22, i02=a01*a12-a02*a11;
        float i10=a12*a20-a10*a22, i11=a00*a22-a02*a20, i12=a02*a10-a00*a12;
        float i20=a10*a21-a11*a20, i21=a01*a20-a00*a21, i22=a00*a11-a01*a10;
        float idet = 1.0f / (a00*i00 + a01*i10 + a02*i20);
        float px = x_pix[ray*2+0], py = x_pix[ray*2+1];
        float dcx=(i00*px+i01*py+i02)*idet, dcy=(i10*px+i11*py+i12)*idet, dcz=(i20*px+i21*py+i22)*idet;
        const float* M = c2w + b * 16;
        float rdx=M[0]*dcx+M[1]*dcy+M[2]*dcz, rdy=M[4]*dcx+M[5]*dcy+M[6]*dcz, rdz=M[8]*dcx+M[9]*dcy+M[10]*dcz;
        float rox=M[3], roy=M[7], roz=M[11];

        int k = tid;  // one hidden unit per thread
        float w0=W1[k], w1=W1[HID+k], w2=W1[2*HID+k];
        ac_s[k] = make_float2(rox*w0 + roy*w1 + roz*w2 + b1[k],
                              rdx*w0 + rdy*w1 + rdz*w2);
        w3_s[tid] = ((const float4*)W3)[tid];
        b2_s[tid] = b2[tid];
        #pragma unroll
        for (int i = 0; i < 4; i++) red[tid + i*256] = 0.0f;
    }
    __syncthreads();

    // --- per-lane row z values (rows = samples of this ray) ---
    const int r0 = warpM * 32 + g;
    float zr[4];
    #pragma unroll
    for (int i = 0; i < 4; i++) zr[i] = fmaf((float)(r0 + i*8), STEPZ, 1.0f);
    // zr[0],zr[1] -> m-tile 0 (rows g, g+8); zr[2],zr[3] -> m-tile 1

    float d[2][8][4];
    #pragma unroll
    for (int mt = 0; mt < 2; mt++)
        #pragma unroll
        for (int nt = 0; nt < 8; nt++)
            #pragma unroll
            for (int i = 0; i < 4; i++) d[mt][nt][i] = 0.0f;

    // --- main loop: 8 slabs x 4 k-steps (k8) ---
    #pragma unroll 1
    for (int s = 0; s < NSLAB; s++) {
        const int buf = s & 1;
        MBAR_WAIT(mb0 + buf*8, (uint32_t)((s >> 1) & 1));
        const float* slab = (const float*)(sm + OFF_SLAB + buf*SLAB_BYTES);

        #pragma unroll
        for (int ks = 0; ks < 4; ks++) {
            const int k0 = s*32 + ks*8 + tig;
            float2 ac0 = ac_s[k0];
            float2 ac1 = ac_s[k0 + 4];
            uint32_t aF[2][4];
            aF[0][0] = f2tf32(fmaxf(fmaf(zr[0], ac0.y, ac0.x), 0.0f));
            aF[0][1] = f2tf32(fmaxf(fmaf(zr[1], ac0.y, ac0.x), 0.0f));
            aF[0][2] = f2tf32(fmaxf(fmaf(zr[0], ac1.y, ac1.x), 0.0f));
            aF[0][3] = f2tf32(fmaxf(fmaf(zr[1], ac1.y, ac1.x), 0.0f));
            aF[1][0] = f2tf32(fmaxf(fmaf(zr[2], ac0.y, ac0.x), 0.0f));
            aF[1][1] = f2tf32(fmaxf(fmaf(zr[3], ac0.y, ac0.x), 0.0f));
            aF[1][2] = f2tf32(fmaxf(fmaf(zr[2], ac1.y, ac1.x), 0.0f));
            aF[1][3] = f2tf32(fmaxf(fmaf(zr[3], ac1.y, ac1.x), 0.0f));

            const float* brow = slab + (ks*8 + tig)*KPAD + warpN*64 + g;
            #pragma unroll
            for (int nt = 0; nt < 8; nt++) {
                uint32_t b0 = __float_as_uint(brow[nt*8]);
                uint32_t b1v = __float_as_uint(brow[nt*8 + 4*KPAD]);
                mma8(d[0][nt], aF[0], b0, b1v);
                mma8(d[1][nt], aF[1], b0, b1v);
            }
        }
        __syncthreads();   // all warps done reading buf before overwrite
        if (tid == 0 && s + 2 < NSLAB) {
            MBAR_EXPECT_TX(mb0 + buf*8, SLAB_BYTES);
            bulk_g2s(smb + OFF_SLAB + buf*SLAB_BYTES, &W2s_g[(s+2)*SLAB_FLOATS],
                     SLAB_BYTES, mb0 + buf*8);
        }
    }

    // --- fused epilogue: bias + relu + layer-3 per lane ---
    float4 acc[4];
    #pragma unroll
    for (int i = 0; i < 4; i++) acc[i] = make_float4(0.f, 0.f, 0.f, 0.f);
    // acc[mt*2 + 0] : row g + mt*16 ; acc[mt*2 + 1] : row g+8 + mt*16

    #pragma unroll
    for (int mt = 0; mt < 2; mt++) {
        #pragma unroll
        for (int nt = 0; nt < 8; nt++) {
            const int j0 = warpN*64 + nt*8 + 2*tig;
            float b2a = b2_s[j0], b2b = b2_s[j0+1];
            float4 w3a = w3_s[j0], w3b = w3_s[j0+1];
            float h00 = fmaxf(d[mt][nt][0] + b2a, 0.0f);
            float h01 = fmaxf(d[mt][nt][1] + b2b, 0.0f);
            float h10 = fmaxf(d[mt][nt][2] + b2a, 0.0f);
            float h11 = fmaxf(d[mt][nt][3] + b2b, 0.0f);
            float4& aA = acc[mt*2 + 0];
            aA.x = fmaf(h00, w3a.x, fmaf(h01, w3b.x, aA.x));
            aA.y = fmaf(h00, w3a.y, fmaf(h01, w3b.y, aA.y));
            aA.z = fmaf(h00, w3a.z, fmaf(h01, w3b.z, aA.z));
            aA.w = fmaf(h00, w3a.w, fmaf(h01, w3b.w, aA.w));
            float4& aB = acc[mt*2 + 1];
            aB.x = fmaf(h10, w3a.x, fmaf(h11, w3b.x, aB.x));
            aB.y = fmaf(h10, w3a.y, fmaf(h11, w3b.y, aB.y));
            aB.z = fmaf(h10, w3a.z, fmaf(h11, w3b.z, aB.z));
            aB.w = fmaf(h10, w3a.w, fmaf(h11, w3b.w, aB.w));
        }
    }

    // quad reduction over tig (lanes g*4 + tig)
    #pragma unroll
    for (int off = 1; off <= 2; off <<= 1) {
        #pragma unroll
        for (int i = 0; i < 4; i++) {
            acc[i].x += __shfl_xor_sync(0xFFFFFFFF, acc[i].x, off);
            acc[i].y += __shfl_xor_sync(0xFFFFFFFF, acc[i].y, off);
            acc[i].z += __shfl_xor_sync(0xFFFFFFFF, acc[i].z, off);
            acc[i].w += __shfl_xor_sync(0xFFFFFFFF, acc[i].w, off);
        }
    }
    if (tig == 0) {
        #pragma unroll
        for (int i = 0; i < 4; i++) {
            int row = warpM*32 + (i >> 1)*16 + (i & 1)*8 + g;
            float* dst = &red[(warpN*64 + row)*4];
            dst[0] = acc[i].x; dst[1] = acc[i].y; dst[2] = acc[i].z; dst[3] = acc[i].w;
        }
    }
    __syncthreads();

    // --- per-sample alpha / sigmoid ---
    if (tid < NS) {
        const int s = tid;
        float o0 = b3[0], o1 = b3[1], o2 = b3[2], o3 = b3[3];
        #pragma unroll
        for (int wn = 0; wn < 4; wn++) {
            const float* p = &red[(wn*64 + s)*4];
            o0 += p[0]; o1 += p[1]; o2 += p[2]; o3 += p[3];
        }
        float dist = (s < NS-1) ? STEPZ : (1000.0f - 6.0f);
        float sg = fmaxf(o0, 0.0f);
        alph[s] = 1.0f - __expf(-sg * dist);
        rr_[s] = 1.0f / (1.0f + __expf(-o1));
        gg_[s] = 1.0f / (1.0f + __expf(-o2));
        bb_[s] = 1.0f / (1.0f + __expf(-o3));
    }
    __syncthreads();

    // --- serial transmittance scan ---
    if (tid == 0) {
        const int ray = blockIdx.x;
        float T = 1.0f, Rc = 0.f, Gc = 0.f, Bc = 0.f, D = 0.f, A = 0.f;
        #pragma unroll
        for (int s = 0; s < NS; s++) {
            float al = alph[s];
            T *= (1.0f - al);                  // inclusive cumprod (matches ref)
            float w = al * T;
            Rc = fmaf(w, rr_[s], Rc);
            Gc = fmaf(w, gg_[s], Gc);
            Bc = fmaf(w, bb_[s], Bc);
            D  = fmaf(w, fmaf((float)s, STEPZ, 1.0f), D);
            A += w;
        }
        float bg = 1.0f - A;
        out[ray*3 + 0] = Rc + bg;
        out[ray*3 + 1] = Gc + bg;
        out[ray*3 + 2] = Bc + bg;
        out[nrays*3 + ray] = D;
        MBAR_INVAL(mb0);
        MBAR_INVAL(mb0 + 8);
    }
}

extern "C" void kernel_launch(void* const* d_in, const int* in_sizes, int n_in,
                              void* d_out, int out_size)
{
    const float* x_pix = (const float*)d_in[0];
    const float* intr  = (const float*)d_in[1];
    const float* c2w   = (const float*)d_in[2];
    const float* W1    = (const float*)d_in[3];
    const float* b1    = (const float*)d_in[4];
    const float* W2    = (const float*)d_in[5];
    const float* b2    = (const float*)d_in[6];
    const float* W3    = (const float*)d_in[7];
    const float* b3    = (const float*)d_in[8];
    float* out = (float*)d_out;

    int nrays = in_sizes[0] / 2;
    int B     = in_sizes[1] / 9;
    int R     = nrays / B;

    arrange_w2_kernel<<<256, 256>>>(W2);

    cudaFuncSetAttribute(nerf_mma_kernel,
                         cudaFuncAttributeMaxDynamicSharedMemorySize, SMEM_TOTAL);
    nerf_mma_kernel<<<nrays, 256, SMEM_TOTAL>>>(
        x_pix, intr, c2w, W1, b1, b2, W3, b3, out, nrays, R);
}

// round 5
// speedup vs baseline: 5.0816x; 1.3427x over previous
#include <cuda_runtime.h>
#include <cuda_fp16.h>
#include <cstdint>

#define NS     64
#define HID    256
#define STEPZ  (5.0f/63.0f)
#define NSLAB  8
#define ROWU32 260                       // uint32 per kp-row (256 + 4 pad)
#define ROWB   (ROWU32*4)                // 1040 bytes
#define SLAB_U32  (16*ROWU32)            // 4160 (16 kp-rows = 32 k per slab)
#define SLAB_BYTES (SLAB_U32*4)          // 16640

// ---- shared memory byte offsets ----
#define OFF_SLAB 0                          // 2 x 16640 = 33280
#define OFF_AC   (2*SLAB_BYTES)             // 33280 : float2 ac[2][256] (4096)
#define OFF_W3   (OFF_AC + 4096)            // 37376 : float4 W3[256]    (4096)
#define OFF_B2   (OFF_W3 + 4096)            // 41472 : float b2[256]     (1024)
#define OFF_RED  (OFF_B2 + 1024)            // 42496 : float red[2][128][4] (4096)
#define OFF_AUX  (OFF_RED + 4096)           // 46592 : alpha/r/g/b [128] (2048)
#define OFF_MBAR (OFF_AUX + 2048)           // 48640 : 2 mbarriers
#define SMEM_TOTAL (OFF_MBAR + 32)          // 48672

// W2 pre-packed: [slab][kp_row 16][np 256(+pad)] f16x2 (k even lo, k odd hi)
__device__ __align__(16) uint32_t W2h_g[NSLAB * SLAB_U32];

// =================== PTX helpers (base-target only) ===================
__device__ __forceinline__ uint32_t smem_u32(const void* p) {
    uint32_t a;
    asm("{ .reg .u64 t; cvta.to.shared.u64 t, %1; cvt.u32.u64 %0, t; }" : "=r"(a) : "l"(p));
    return a;
}
#define MBAR_INIT(a, c) \
    asm volatile("mbarrier.init.shared.b64 [%0], %1;" :: "r"(a), "r"((uint32_t)(c)) : "memory")
#define MBAR_EXPECT_TX(a, b) \
    asm volatile("mbarrier.arrive.expect_tx.shared.b64 _, [%0], %1;" :: "r"(a), "r"((uint32_t)(b)) : "memory")
#define MBAR_INVAL(a) \
    asm volatile("mbarrier.inval.shared.b64 [%0];" :: "r"(a) : "memory")
#define MBAR_WAIT(a, ph) do {                                                   \
    uint32_t _m = (a); uint32_t _p = (ph); uint32_t _d;                         \
    asm volatile("{\n\t.reg .pred p;\n\t"                                       \
        "mbarrier.try_wait.parity.acquire.cta.shared::cta.b64 p, [%1], %2;\n\t" \
        "selp.b32 %0, 1, 0, p;\n\t}" : "=r"(_d) : "r"(_m), "r"(_p) : "memory"); \
    if (!_d) {                                                                  \
        asm volatile("{\n\t.reg .pred P1;\n\t"                                  \
        "WL_%=:\n\t"                                                            \
        "mbarrier.try_wait.parity.acquire.cta.shared::cta.b64 P1, [%0], %1, 0x989680;\n\t" \
        "@P1 bra.uni WD_%=;\n\t bra.uni WL_%=;\n\t WD_%=:\n\t}"                 \
        :: "r"(_m), "r"(_p) : "memory");                                        \
    } } while (0)

__device__ __forceinline__ void bulk_g2s(uint32_t dst, const void* src, uint32_t bytes, uint32_t mbar) {
    asm volatile("cp.async.bulk.shared::cta.global.mbarrier::complete_tx::bytes [%0], [%1], %2, [%3];"
                 :: "r"(dst), "l"(src), "r"(bytes), "r"(mbar) : "memory");
}
// pack two fp32 -> f16x2 (lo = e, hi = o)
__device__ __forceinline__ uint32_t packh(float e, float o) {
    uint32_t r; asm("cvt.rn.f16x2.f32 %0, %1, %2;" : "=r"(r) : "f"(o), "f"(e)); return r;
}
__device__ __forceinline__ void mma16(float* d, const uint32_t* a, uint32_t b0, uint32_t b1) {
    asm volatile("mma.sync.aligned.m16n8k16.row.col.f32.f16.f16.f32 "
        "{%0,%1,%2,%3}, {%4,%5,%6,%7}, {%8,%9}, {%0,%1,%2,%3};"
        : "+f"(d[0]), "+f"(d[1]), "+f"(d[2]), "+f"(d[3])
        : "r"(a[0]), "r"(a[1]), "r"(a[2]), "r"(a[3]), "r"(b0), "r"(b1));
}

// =================== kernel 1: pack W2 to f16x2, permuted layout ===================
__global__ void arrange_w2_kernel(const float* __restrict__ W2) {
    int idx = blockIdx.x * 256 + threadIdx.x;       // 0..32767
    int kp = idx >> 8, n = idx & 255;               // kp = k/2 (0..127)
    float e = W2[(2*kp)     * HID + n];
    float o = W2[(2*kp + 1) * HID + n];
    int slab = kp >> 4;                             // 16 kp-rows per slab
    int sub  = (kp >> 3) & 1;                       // k16-step within slab
    int t    = kp & 7;                              // kpair within k16
    int np   = (n & ~63) | ((n & 7) << 3) | ((n >> 3) & 7);
    W2h_g[slab * SLAB_U32 + (sub * 8 + t) * ROWU32 + np] = packh(e, o);
}

// =================== kernel 2: fused renderer (2 rays / CTA, M=128) ===================
__global__ __launch_bounds__(256)
void nerf_mma_kernel(const float* __restrict__ x_pix,
                     const float* __restrict__ intr,
                     const float* __restrict__ c2w,
                     const float* __restrict__ W1, const float* __restrict__ b1,
                     const float* __restrict__ b2,
                     const float* __restrict__ W3, const float* __restrict__ b3,
                     float* __restrict__ out, int nrays, int R)
{
    extern __shared__ char sm[];
    const uint32_t smb = smem_u32(sm);
    float2* ac_s = (float2*)(sm + OFF_AC);      // [2 rays][256]
    float4* w3_s = (float4*)(sm + OFF_W3);
    float*  b2_s = (float*)(sm + OFF_B2);
    float*  red  = (float*)(sm + OFF_RED);      // [2 warpN][128 p][4 ch]
    float*  alph = (float*)(sm + OFF_AUX);      // [128]
    float*  rr_  = alph + 128; float* gg_ = rr_ + 128; float* bb_ = gg_ + 128;

    const uint32_t mb0 = smb + OFF_MBAR;

    const int tid  = threadIdx.x;
    const int lane = tid & 31, warp = tid >> 5;
    const int warpM = warp >> 1, warpN = warp & 1;   // 4(M) x 2(N) warp grid
    const int g = lane >> 2, tig = lane & 3;
    const int rl = warpM >> 1;                       // ray-local of this warp

    if (tid == 0) {
        MBAR_INIT(mb0, 1);
        MBAR_INIT(mb0 + 8, 1);
        MBAR_EXPECT_TX(mb0, SLAB_BYTES);
        bulk_g2s(smb + OFF_SLAB, &W2h_g[0], SLAB_BYTES, mb0);
        MBAR_EXPECT_TX(mb0 + 8, SLAB_BYTES);
        bulk_g2s(smb + OFF_SLAB + SLAB_BYTES, &W2h_g[SLAB_U32], SLAB_BYTES, mb0 + 8);
    }

    // --- setup: (a,c) tables for both rays, stage W3/b2 ---
    #pragma unroll
    for (int r = 0; r < 2; r++) {
        const int ray = blockIdx.x * 2 + r;
        const int b   = ray / R;
        const float* Km = intr + b * 9;
        float a00=Km[0],a01=Km[1],a02=Km[2],a10=Km[3],a11=Km[4],a12=Km[5],a20=Km[6],a21=Km[7],a22=Km[8];
        float i00=a11*a22-a12*a21, i01=a02*a21-a01*a22, i02=a01*a12-a02*a11;
        float i10=a12*a20-a10*a22, i11=a00*a22-a02*a20, i12=a02*a10-a00*a12;
        float i20=a10*a21-a11*a20, i21=a01*a20-a00*a21, i22=a00*a11-a01*a10;
        float idet = 1.0f / (a00*i00 + a01*i10 + a02*i20);
        float px = x_pix[ray*2+0], py = x_pix[ray*2+1];
        float dcx=(i00*px+i01*py+i02)*idet, dcy=(i10*px+i11*py+i12)*idet, dcz=(i20*px+i21*py+i22)*idet;
        const float* M = c2w + b * 16;
        float rdx=M[0]*dcx+M[1]*dcy+M[2]*dcz, rdy=M[4]*dcx+M[5]*dcy+M[6]*dcz, rdz=M[8]*dcx+M[9]*dcy+M[10]*dcz;
        float rox=M[3], roy=M[7], roz=M[11];

        int k = tid;
        float w0=W1[k], w1=W1[HID+k], w2=W1[2*HID+k];
        ac_s[r*HID + k] = make_float2(rox*w0 + roy*w1 + roz*w2 + b1[k],
                                      rdx*w0 + rdy*w1 + rdz*w2);
    }
    w3_s[tid] = ((const float4*)W3)[tid];
    b2_s[tid] = b2[tid];
    __syncthreads();

    // --- per-warp row z values: s-rows (warpM&1)*32 + mt*16 + {g, g+8} ---
    float zr[2][2];
    #pragma unroll
    for (int mt = 0; mt < 2; mt++) {
        int s0 = (warpM & 1) * 32 + mt * 16 + g;
        zr[mt][0] = fmaf((float)s0, STEPZ, 1.0f);
        zr[mt][1] = fmaf((float)(s0 + 8), STEPZ, 1.0f);
    }

    float d[2][16][4];
    #pragma unroll
    for (int mt = 0; mt < 2; mt++)
        #pragma unroll
        for (int nt = 0; nt < 16; nt++)
            #pragma unroll
            for (int i = 0; i < 4; i++) d[mt][nt][i] = 0.0f;

    const uint32_t bcol = (uint32_t)(warpN * 2 * 64 + g * 8) * 4;   // byte offset in row

    // --- main loop: 8 slabs x 2 k16-steps ---
    #pragma unroll 1
    for (int s = 0; s < NSLAB; s++) {
        const int buf = s & 1;
        MBAR_WAIT(mb0 + buf*8, (uint32_t)((s >> 1) & 1));
        const char* slab = sm + OFF_SLAB + buf*SLAB_BYTES;

        #pragma unroll
        for (int sub = 0; sub < 2; sub++) {
            const int kbase = s*32 + sub*16;
            // A fragments: h = relu(a + z*c), packed f16x2 over k-pairs
            float4 acA = *(const float4*)&ac_s[rl*HID + kbase + 2*tig];
            float4 acB = *(const float4*)&ac_s[rl*HID + kbase + 2*tig + 8];
            uint32_t aF[2][4];
            #pragma unroll
            for (int mt = 0; mt < 2; mt++) {
                float z0 = zr[mt][0], z1 = zr[mt][1];
                aF[mt][0] = packh(fmaxf(fmaf(z0, acA.y, acA.x), 0.f),
                                  fmaxf(fmaf(z0, acA.w, acA.z), 0.f));
                aF[mt][1] = packh(fmaxf(fmaf(z1, acA.y, acA.x), 0.f),
                                  fmaxf(fmaf(z1, acA.w, acA.z), 0.f));
                aF[mt][2] = packh(fmaxf(fmaf(z0, acB.y, acB.x), 0.f),
                                  fmaxf(fmaf(z0, acB.w, acB.z), 0.f));
                aF[mt][3] = packh(fmaxf(fmaf(z1, acB.y, acB.x), 0.f),
                                  fmaxf(fmaf(z1, acB.w, acB.z), 0.f));
            }

            // B fragments: 8 x LDS.128 (16 n-tiles, k-pairs packed)
            const char* row0 = slab + (sub*8 + tig    ) * ROWB + bcol;
            const char* row1 = slab + (sub*8 + tig + 4) * ROWB + bcol;
            uint4 b0a = *(const uint4*)(row0);
            uint4 b0b = *(const uint4*)(row0 + 16);
            uint4 b0c = *(const uint4*)(row0 + 256);
            uint4 b0d = *(const uint4*)(row0 + 272);
            uint4 b1a = *(const uint4*)(row1);
            uint4 b1b = *(const uint4*)(row1 + 16);
            uint4 b1c = *(const uint4*)(row1 + 256);
            uint4 b1d = *(const uint4*)(row1 + 272);
            uint32_t b0s[16] = {b0a.x,b0a.y,b0a.z,b0a.w, b0b.x,b0b.y,b0b.z,b0b.w,
                                b0c.x,b0c.y,b0c.z,b0c.w, b0d.x,b0d.y,b0d.z,b0d.w};
            uint32_t b1s[16] = {b1a.x,b1a.y,b1a.z,b1a.w, b1b.x,b1b.y,b1b.z,b1b.w,
                                b1c.x,b1c.y,b1c.z,b1c.w, b1d.x,b1d.y,b1d.z,b1d.w};

            #pragma unroll
            for (int nt = 0; nt < 16; nt++) {
                mma16(d[0][nt], aF[0], b0s[nt], b1s[nt]);
                mma16(d[1][nt], aF[1], b0s[nt], b1s[nt]);
            }
        }
        __syncthreads();   // all warps done reading buf before overwrite
        if (tid == 0 && s + 2 < NSLAB) {
            MBAR_EXPECT_TX(mb0 + buf*8, SLAB_BYTES);
            bulk_g2s(smb + OFF_SLAB + buf*SLAB_BYTES, &W2h_g[(s+2)*SLAB_U32],
                     SLAB_BYTES, mb0 + buf*8);
        }
    }

    // --- fused epilogue: bias + relu + layer-3 per lane ---
    float4 acc[2][2];
    #pragma unroll
    for (int mt = 0; mt < 2; mt++)
        #pragma unroll
        for (int i = 0; i < 2; i++) acc[mt][i] = make_float4(0.f, 0.f, 0.f, 0.f);

    #pragma unroll
    for (int mt = 0; mt < 2; mt++) {
        #pragma unroll
        for (int nt = 0; nt < 16; nt++) {
            const int j0 = warpN*128 + nt*8 + 2*tig;
            float b2a = b2_s[j0], b2b = b2_s[j0+1];
            float4 w3a = w3_s[j0], w3b = w3_s[j0+1];
            float h00 = fmaxf(d[mt][nt][0] + b2a, 0.0f);
            float h01 = fmaxf(d[mt][nt][1] + b2b, 0.0f);
            float h10 = fmaxf(d[mt][nt][2] + b2a, 0.0f);
            float h11 = fmaxf(d[mt][nt][3] + b2b, 0.0f);
            float4& aA = acc[mt][0];
            aA.x = fmaf(h00, w3a.x, fmaf(h01, w3b.x, aA.x));
            aA.y = fmaf(h00, w3a.y, fmaf(h01, w3b.y, aA.y));
            aA.z = fmaf(h00, w3a.z, fmaf(h01, w3b.z, aA.z));
            aA.w = fmaf(h00, w3a.w, fmaf(h01, w3b.w, aA.w));
            float4& aB = acc[mt][1];
            aB.x = fmaf(h10, w3a.x, fmaf(h11, w3b.x, aB.x));
            aB.y = fmaf(h10, w3a.y, fmaf(h11, w3b.y, aB.y));
            aB.z = fmaf(h10, w3a.z, fmaf(h11, w3b.z, aB.z));
            aB.w = fmaf(h10, w3a.w, fmaf(h11, w3b.w, aB.w));
        }
    }

    #pragma unroll
    for (int off = 1; off <= 2; off <<= 1) {
        #pragma unroll
        for (int mt = 0; mt < 2; mt++)
            #pragma unroll
            for (int i = 0; i < 2; i++) {
                acc[mt][i].x += __shfl_xor_sync(0xFFFFFFFF, acc[mt][i].x, off);
                acc[mt][i].y += __shfl_xor_sync(0xFFFFFFFF, acc[mt][i].y, off);
                acc[mt][i].z += __shfl_xor_sync(0xFFFFFFFF, acc[mt][i].z, off);
                acc[mt][i].w += __shfl_xor_sync(0xFFFFFFFF, acc[mt][i].w, off);
            }
    }
    if (tig == 0) {
        #pragma unroll
        for (int mt = 0; mt < 2; mt++)
            #pragma unroll
            for (int i = 0; i < 2; i++) {
                int p = rl*64 + (warpM & 1)*32 + mt*16 + i*8 + g;
                float* dst = &red[(warpN*128 + p)*4];
                dst[0] = acc[mt][i].x; dst[1] = acc[mt][i].y;
                dst[2] = acc[mt][i].z; dst[3] = acc[mt][i].w;
            }
    }
    __syncthreads();

    // --- per-sample alpha / sigmoid (p = ray_local*64 + s) ---
    if (tid < 128) {
        const int p = tid, ss = tid & 63;
        const float* p0 = &red[p*4];
        const float* p1 = &red[(128 + p)*4];
        float o0 = b3[0] + p0[0] + p1[0];
        float o1 = b3[1] + p0[1] + p1[1];
        float o2 = b3[2] + p0[2] + p1[2];
        float o3 = b3[3] + p0[3] + p1[3];
        float dist = (ss < NS-1) ? STEPZ : (1000.0f - 6.0f);
        float sg = fmaxf(o0, 0.0f);
        alph[p] = 1.0f - __expf(-sg * dist);
        rr_[p] = 1.0f / (1.0f + __expf(-o1));
        gg_[p] = 1.0f / (1.0f + __expf(-o2));
        bb_[p] = 1.0f / (1.0f + __expf(-o3));
    }
    __syncthreads();

    // --- serial transmittance scan, one thread per ray ---
    if (tid < 2) {
        const int base = tid * 64;
        const int ray = blockIdx.x * 2 + tid;
        float T = 1.0f, Rc = 0.f, Gc = 0.f, Bc = 0.f, D = 0.f, A = 0.f;
        #pragma unroll
        for (int ss = 0; ss < NS; ss++) {
            float al = alph[base + ss];
            T *= (1.0f - al);                  // inclusive cumprod (matches ref)
            float w = al * T;
            Rc = fmaf(w, rr_[base + ss], Rc);
            Gc = fmaf(w, gg_[base + ss], Gc);
            Bc = fmaf(w, bb_[base + ss], Bc);
            D  = fmaf(w, fmaf((float)ss, STEPZ, 1.0f), D);
            A += w;
        }
        float bg = 1.0f - A;
        out[ray*3 + 0] = Rc + bg;
        out[ray*3 + 1] = Gc + bg;
        out[ray*3 + 2] = Bc + bg;
        out[nrays*3 + ray] = D;
    }

    if (tid == 0) { MBAR_INVAL(mb0); MBAR_INVAL(mb0 + 8); }
}

extern "C" void kernel_launch(void* const* d_in, const int* in_sizes, int n_in,
                              void* d_out, int out_size)
{
    const float* x_pix = (const float*)d_in[0];
    const float* intr  = (const float*)d_in[1];
    const float* c2w   = (const float*)d_in[2];
    const float* W1    = (const float*)d_in[3];
    const float* b1    = (const float*)d_in[4];
    const float* W2    = (const float*)d_in[5];
    const float* b2    = (const float*)d_in[6];
    const float* W3    = (const float*)d_in[7];
    const float* b3    = (const float*)d_in[8];
    float* out = (float*)d_out;

    int nrays = in_sizes[0] / 2;
    int B     = in_sizes[1] / 9;
    int R     = nrays / B;

    arrange_w2_kernel<<<128, 256>>>(W2);

    cudaFuncSetAttribute(nerf_mma_kernel,
                         cudaFuncAttributeMaxDynamicSharedMemorySize, SMEM_TOTAL);
    nerf_mma_kernel<<<nrays/2, 256, SMEM_TOTAL>>>(
        x_pix, intr, c2w, W1, b1, b2, W3, b3, out, nrays, R);
}